// round 3
// baseline (speedup 1.0000x reference)
#include <cuda_runtime.h>
#include <cuda_bf16.h>
#include <mma.h>
#include <cstdint>

using namespace nvcuda;

// Problem constants
constexpr int Bq = 8;
constexpr int T  = 200;
constexpr int U  = 50;
constexpr int D  = 512;    // K
constexpr int V  = 1024;   // N
constexpr int M_ENC  = Bq * T;          // 1600
constexpr int M_TOT  = M_ENC + Bq * U;  // 2000
constexpr int M_PAD  = 2048;

// GEMM tiling
constexpr int BM   = 128;
constexpr int BN   = 128;
constexpr int KC   = 8;            // k-chunk per pipeline stage
constexpr int NS   = D / KC;       // 64 stages
constexpr int NBUF = 4;            // 3-deep cp.async pipeline
constexpr int PAD  = 4;
constexpr int LDS_ = KC + PAD;     // 12 floats (48B) row stride

// Scratch: EP[m, v]  (rows 0..1599 = enc@W^T, rows 1600..1999 = pred@W^T)
__device__ float EP[M_PAD * V];

__device__ __forceinline__ void cp_async16(float* smem_dst, const float* gsrc, int src_bytes) {
    uint32_t s = (uint32_t)__cvta_generic_to_shared(smem_dst);
    asm volatile("cp.async.cg.shared.global [%0], [%1], 16, %2;\n"
                 :: "r"(s), "l"(gsrc), "r"(src_bytes));
}
__device__ __forceinline__ void cp_commit() {
    asm volatile("cp.async.commit_group;\n" ::);
}

// ---------------------------------------------------------------------------
// Kernel 1: EP = [enc; pred] @ W^T  (tf32 wmma, fp32 accum, 3-deep pipeline)
// ---------------------------------------------------------------------------
__global__ __launch_bounds__(256)
void joiner_gemm_kernel(const float* __restrict__ enc,
                        const float* __restrict__ pred,
                        const float* __restrict__ W)
{
    // 4 buffers x (128 + 128) rows x 12 floats x 4B = 49152 B (exactly 48 KB)
    __shared__ float As[NBUF][BM * LDS_];
    __shared__ float Bs[NBUF][BN * LDS_];

    const int m0 = blockIdx.y * BM;
    const int n0 = blockIdx.x * BN;
    const int tid  = threadIdx.x;        // 256
    const int warp = tid >> 5;           // 8 warps: 2 (M) x 4 (N)
    const int wm   = (warp >> 2) * 64;   // 0 / 64
    const int wn   = (warp & 3)  * 32;   // 0..96

    // A/B stage-load indices: 256 chunks of 16B per tile, 1 per thread
    const int lr = tid >> 1;             // row 0..127
    const int lc = (tid & 1) * 4;        // 0 / 4

    wmma::fragment<wmma::accumulator, 16, 16, 8, float> acc[4][2];
#pragma unroll
    for (int i = 0; i < 4; i++)
#pragma unroll
        for (int j = 0; j < 2; j++)
            wmma::fill_fragment(acc[i][j], 0.0f);

    auto load_stage = [&](int ks, int buf) {
        const int k0 = ks * KC;
        // A tile
        {
            const int gr = m0 + lr;
            const float* src = enc;
            int sz = 0;
            if (gr < M_ENC)      { src = enc  + (size_t)gr * D + k0 + lc;           sz = 16; }
            else if (gr < M_TOT) { src = pred + (size_t)(gr - M_ENC) * D + k0 + lc; sz = 16; }
            cp_async16(&As[buf][lr * LDS_ + lc], src, sz);
        }
        // B tile
        cp_async16(&Bs[buf][lr * LDS_ + lc], W + (size_t)(n0 + lr) * D + k0 + lc, 16);
        cp_commit();
    };

    // prologue: 3 stages in flight
#pragma unroll
    for (int s = 0; s < 3; s++) load_stage(s, s);

    for (int ks = 0; ks < NS; ks++) {
        const int buf = ks & (NBUF - 1);
        const int rem = NS - 1 - ks;  // stages allowed to remain outstanding
        if (rem >= 2)      asm volatile("cp.async.wait_group 2;\n" ::);
        else if (rem == 1) asm volatile("cp.async.wait_group 1;\n" ::);
        else               asm volatile("cp.async.wait_group 0;\n" ::);
        __syncthreads();

        if (ks + 3 < NS) load_stage(ks + 3, (ks + 3) & (NBUF - 1));

        wmma::fragment<wmma::matrix_a, 16, 16, 8, wmma::precision::tf32, wmma::row_major> af[4];
        wmma::fragment<wmma::matrix_b, 16, 16, 8, wmma::precision::tf32, wmma::col_major> bf[2];
#pragma unroll
        for (int i = 0; i < 4; i++) {
            wmma::load_matrix_sync(af[i], &As[buf][(wm + i * 16) * LDS_], LDS_);
#pragma unroll
            for (int t = 0; t < af[i].num_elements; t++)
                af[i].x[t] = wmma::__float_to_tf32(af[i].x[t]);
        }
#pragma unroll
        for (int j = 0; j < 2; j++) {
            wmma::load_matrix_sync(bf[j], &Bs[buf][(wn + j * 16) * LDS_], LDS_);
#pragma unroll
            for (int t = 0; t < bf[j].num_elements; t++)
                bf[j].x[t] = wmma::__float_to_tf32(bf[j].x[t]);
        }
#pragma unroll
        for (int i = 0; i < 4; i++)
#pragma unroll
            for (int j = 0; j < 2; j++)
                wmma::mma_sync(acc[i][j], af[i], bf[j], acc[i][j]);
    }

    __syncthreads();
#pragma unroll
    for (int i = 0; i < 4; i++)
#pragma unroll
        for (int j = 0; j < 2; j++)
            wmma::store_matrix_sync(&EP[(size_t)(m0 + wm + i * 16) * V + (n0 + wn + j * 16)],
                                    acc[i][j], V, wmma::mem_row_major);
}

// ---------------------------------------------------------------------------
// Kernel 2: out[b,t,u,v] = EP[b*T+t, v] + EP[1600 + b*U+u, v] + bias[v]
//   Plain streaming STG.128 (stcs regressed); single balanced resident wave.
// ---------------------------------------------------------------------------
constexpr int BCAST_GRID = 1184;   // 148 SMs x 8 resident CTAs: one wave

__global__ __launch_bounds__(256, 8)
void joiner_bcast_kernel(const float* __restrict__ bias,
                         float* __restrict__ out)
{
    const int tid = threadIdx.x;         // 256 threads * 4 floats = V
    const float4 bb = *reinterpret_cast<const float4*>(bias + tid * 4);

    for (int bt = blockIdx.x; bt < M_ENC; bt += BCAST_GRID) {
        const int b = bt / T;

        float4 e = *reinterpret_cast<const float4*>(EP + (size_t)bt * V + tid * 4);
        e.x += bb.x; e.y += bb.y; e.z += bb.z; e.w += bb.w;

        const float* Pbase = EP + (size_t)(M_ENC + b * U) * V + tid * 4;
        float*       Obase = out + (size_t)bt * U * V + tid * 4;

#pragma unroll 10
        for (int u = 0; u < U; u++) {
            float4 p = *reinterpret_cast<const float4*>(Pbase + (size_t)u * V);
            float4 o;
            o.x = e.x + p.x;
            o.y = e.y + p.y;
            o.z = e.z + p.z;
            o.w = e.w + p.w;
            *reinterpret_cast<float4*>(Obase + (size_t)u * V) = o;
        }
    }
}

// ---------------------------------------------------------------------------
extern "C" void kernel_launch(void* const* d_in, const int* in_sizes, int n_in,
                              void* d_out, int out_size)
{
    const float* enc  = (const float*)d_in[0];   // [B,T,D]
    const float* pred = (const float*)d_in[1];   // [B,U,D]
    const float* W    = (const float*)d_in[2];   // [V,D]
    const float* bias = (const float*)d_in[3];   // [V]
    float* out = (float*)d_out;                  // [B,T,U,V]

    dim3 ggrid(V / BN, M_PAD / BM);              // 8 x 16 = 128 CTAs
    joiner_gemm_kernel<<<ggrid, 256>>>(enc, pred, W);
    joiner_bcast_kernel<<<BCAST_GRID, 256>>>(bias, out);
}

// round 4
// speedup vs baseline: 1.2124x; 1.2124x over previous
#include <cuda_runtime.h>
#include <cuda_bf16.h>
#include <mma.h>
#include <cstdint>

using namespace nvcuda;

// Problem constants
constexpr int Bq = 8;
constexpr int T  = 200;
constexpr int U  = 50;
constexpr int D  = 512;    // K
constexpr int V  = 1024;   // N
constexpr int M_ENC  = Bq * T;          // 1600
constexpr int M_TOT  = M_ENC + Bq * U;  // 2000
constexpr int M_PAD  = 2048;

// GEMM tiling (round-2 proven config: KC=16, double-buffered cp.async)
constexpr int BM  = 128;
constexpr int BN  = 128;
constexpr int KC  = 16;          // k-chunk per stage
constexpr int NS  = D / KC;      // 32 stages
constexpr int PAD = 4;
constexpr int LDS_ = KC + PAD;   // 20 floats row stride

// Scratch: EP[m, v]  (rows 0..1599 = enc@W^T, rows 1600..1999 = pred@W^T)
__device__ float EP[M_PAD * V];

__device__ __forceinline__ void cp_async16(float* smem_dst, const float* gsrc, int src_bytes) {
    uint32_t s = (uint32_t)__cvta_generic_to_shared(smem_dst);
    asm volatile("cp.async.cg.shared.global [%0], [%1], 16, %2;\n"
                 :: "r"(s), "l"(gsrc), "r"(src_bytes));
}
__device__ __forceinline__ void cp_commit() {
    asm volatile("cp.async.commit_group;\n" ::);
}

// ---------------------------------------------------------------------------
// Kernel 1: EP = [enc; pred] @ W^T  (tf32 wmma, fp32 accum, double buffer)
// ---------------------------------------------------------------------------
__global__ __launch_bounds__(256)
void joiner_gemm_kernel(const float* __restrict__ enc,
                        const float* __restrict__ pred,
                        const float* __restrict__ W)
{
    __shared__ float As[2][BM * LDS_];   // (m, k) row-major, lda = LDS_
    __shared__ float Bs[2][BN * LDS_];   // (n, k): (k,n) at Bs[n*LDS_+k] -> col_major

    const int m0 = blockIdx.y * BM;
    const int n0 = blockIdx.x * BN;
    const int tid  = threadIdx.x;        // 256
    const int warp = tid >> 5;           // 8 warps: 2 (M) x 4 (N)
    const int wm   = (warp >> 2) * 64;   // 0 / 64
    const int wn   = (warp & 3)  * 32;   // 0..96

    wmma::fragment<wmma::accumulator, 16, 16, 8, float> acc[4][2];
#pragma unroll
    for (int i = 0; i < 4; i++)
#pragma unroll
        for (int j = 0; j < 2; j++)
            wmma::fill_fragment(acc[i][j], 0.0f);

    auto load_stage = [&](int ks, int buf) {
        const int k0 = ks * KC;
#pragma unroll
        for (int t = 0; t < 2; t++) {
            const int idx = tid + t * 256;
            const int r   = idx >> 2;          // 4 chunks per 16-float row
            const int c   = (idx & 3) * 4;
            const int gr  = m0 + r;
            const float* src = enc;            // dummy for zero-fill rows
            int sz = 0;
            if (gr < M_ENC)      { src = enc  + (size_t)gr * D + k0 + c;           sz = 16; }
            else if (gr < M_TOT) { src = pred + (size_t)(gr - M_ENC) * D + k0 + c; sz = 16; }
            cp_async16(&As[buf][r * LDS_ + c], src, sz);
        }
#pragma unroll
        for (int t = 0; t < 2; t++) {
            const int idx = tid + t * 256;
            const int n   = idx >> 2;
            const int c   = (idx & 3) * 4;
            cp_async16(&Bs[buf][n * LDS_ + c], W + (size_t)(n0 + n) * D + k0 + c, 16);
        }
        cp_commit();
    };

    load_stage(0, 0);

    for (int ks = 0; ks < NS; ks++) {
        const int buf = ks & 1;
        if (ks + 1 < NS) {
            load_stage(ks + 1, buf ^ 1);
            asm volatile("cp.async.wait_group 1;\n" ::);
        } else {
            asm volatile("cp.async.wait_group 0;\n" ::);
        }
        __syncthreads();

#pragma unroll
        for (int kk = 0; kk < KC; kk += 8) {
            wmma::fragment<wmma::matrix_a, 16, 16, 8, wmma::precision::tf32, wmma::row_major> af[4];
            wmma::fragment<wmma::matrix_b, 16, 16, 8, wmma::precision::tf32, wmma::col_major> bf[2];
#pragma unroll
            for (int i = 0; i < 4; i++) {
                wmma::load_matrix_sync(af[i], &As[buf][(wm + i * 16) * LDS_ + kk], LDS_);
#pragma unroll
                for (int t = 0; t < af[i].num_elements; t++)
                    af[i].x[t] = wmma::__float_to_tf32(af[i].x[t]);
            }
#pragma unroll
            for (int j = 0; j < 2; j++) {
                wmma::load_matrix_sync(bf[j], &Bs[buf][(wn + j * 16) * LDS_ + kk], LDS_);
#pragma unroll
                for (int t = 0; t < bf[j].num_elements; t++)
                    bf[j].x[t] = wmma::__float_to_tf32(bf[j].x[t]);
            }
#pragma unroll
            for (int i = 0; i < 4; i++)
#pragma unroll
                for (int j = 0; j < 2; j++)
                    wmma::mma_sync(acc[i][j], af[i], bf[j], acc[i][j]);
        }
        __syncthreads();
    }

    // store (padded EP rows absorb the M=2000 ragged tail)
#pragma unroll
    for (int i = 0; i < 4; i++)
#pragma unroll
        for (int j = 0; j < 2; j++)
            wmma::store_matrix_sync(&EP[(size_t)(m0 + wm + i * 16) * V + (n0 + wn + j * 16)],
                                    acc[i][j], V, wmma::mem_row_major);
}

// ---------------------------------------------------------------------------
// Kernel 2: out[b,t,u,v] = EP[b*T+t, v] + EP[1600 + b*U+u, v] + bias[v]
//   Round-1 proven config: one CTA per (b,t), plain STG.128, unroll 5.
// ---------------------------------------------------------------------------
__global__ __launch_bounds__(256, 8)
void joiner_bcast_kernel(const float* __restrict__ bias,
                         float* __restrict__ out)
{
    const int bt  = blockIdx.x;          // 0..1599
    const int b   = bt / T;
    const int tid = threadIdx.x;         // 256 threads * 4 floats = V

    float4 e  = *reinterpret_cast<const float4*>(EP + (size_t)bt * V + tid * 4);
    float4 bb = *reinterpret_cast<const float4*>(bias + tid * 4);
    e.x += bb.x; e.y += bb.y; e.z += bb.z; e.w += bb.w;

    const float* Pbase = EP + (size_t)(M_ENC + b * U) * V + tid * 4;
    float*       Obase = out + (size_t)bt * U * V + tid * 4;

#pragma unroll 5
    for (int u = 0; u < U; u++) {
        float4 p = *reinterpret_cast<const float4*>(Pbase + (size_t)u * V);
        float4 o;
        o.x = e.x + p.x;
        o.y = e.y + p.y;
        o.z = e.z + p.z;
        o.w = e.w + p.w;
        *reinterpret_cast<float4*>(Obase + (size_t)u * V) = o;
    }
}

// ---------------------------------------------------------------------------
extern "C" void kernel_launch(void* const* d_in, const int* in_sizes, int n_in,
                              void* d_out, int out_size)
{
    const float* enc  = (const float*)d_in[0];   // [B,T,D]
    const float* pred = (const float*)d_in[1];   // [B,U,D]
    const float* W    = (const float*)d_in[2];   // [V,D]
    const float* bias = (const float*)d_in[3];   // [V]
    float* out = (float*)d_out;                  // [B,T,U,V]

    dim3 ggrid(V / BN, M_PAD / BM);              // 8 x 16 = 128 CTAs
    joiner_gemm_kernel<<<ggrid, 256>>>(enc, pred, W);
    joiner_bcast_kernel<<<M_ENC, 256>>>(bias, out);
}